// round 11
// baseline (speedup 1.0000x reference)
#include <cuda_runtime.h>

#define NB 32
#define NP 256
#define ND 64
#define NT 4096
#define TCHUNK 512   // tasks per CTA (2 per thread)
#define NCHUNK 8     // NT / TCHUNK
#define NWARP 8      // warps per CTA
#define NPART (NCHUNK * NWARP)   // 64 per-warp partials per (b,p)
#define PTILE 16     // p rows staged per smem tile

#define LOG2E (1.4426950408889634f)

typedef unsigned long long u64;

// Per-warp partials: (warp max m, sum exp S, sum exp*pred V, pad)
__device__ float4 g_part[NB * NP * NPART];
__device__ int    g_ready[NB];   // zero-init; reset in-kernel each call

// ---------- packed f32x2 helpers ----------
__device__ __forceinline__ u64 fma2(u64 a, u64 b, u64 acc) {
    u64 r;
    asm("fma.rn.f32x2 %0, %1, %2, %3;" : "=l"(r) : "l"(a), "l"(b), "l"(acc));
    return r;
}
__device__ __forceinline__ u64 add2(u64 a, u64 b) {
    u64 r;
    asm("add.rn.f32x2 %0, %1, %2;" : "=l"(r) : "l"(a), "l"(b));
    return r;
}
__device__ __forceinline__ float2 u2f(u64 a) {
    float2 r;
    asm("mov.b64 {%0, %1}, %2;" : "=f"(r.x), "=f"(r.y) : "l"(a));
    return r;
}

// Warp float-max for values <= 0 in ONE instruction (u32-min over raw bits).
__device__ __forceinline__ float warp_max_nonpos(float x) {
    return __uint_as_float(__reduce_min_sync(0xffffffffu, __float_as_uint(x)));
}

// exp via MUFU: arg <= 0; leader always evaluates ex2(0)=1 exactly.
__device__ __forceinline__ float mufu_exp(float x) {
    float r;
    asm("ex2.approx.f32 %0, %1;" : "=f"(r) : "f"(x * LOG2E));
    return r;
}

// ------------------------------------------------------------------
// CTA = (t-chunk, b). TWO tasks per thread; FOUR p's per inner step
// (four interleaved reduction chains hide SHFL latency). The last
// chunk-CTA per b fuses the LSE combine (no second kernel).
// ------------------------------------------------------------------
__global__ void __launch_bounds__(256, 1)
mmse_main(const float* __restrict__ data,
          const float* __restrict__ targets,
          const float* __restrict__ task_pool,
          float* __restrict__ out)
{
    const int chunk = blockIdx.x;
    const int b     = blockIdx.y;
    const int tid   = threadIdx.x;
    const int lane  = tid & 31;
    const int warp  = tid >> 5;
    const int tA    = chunk * TCHUNK + tid;
    const int tB    = tA + 256;

    __shared__ float stgt[NP];
    __shared__ float srow[2][PTILE][ND];   // 2 x 4KB row tiles
    __shared__ int   sIsLast;

    // Two W columns as packed f32x2 (128 registers)
    u64 wa[32], wb[32];
    {
        const ulonglong2* wpA = (const ulonglong2*)(task_pool + (size_t)tA * ND);
        const ulonglong2* wpB = (const ulonglong2*)(task_pool + (size_t)tB * ND);
        #pragma unroll
        for (int i = 0; i < 16; ++i) {
            ulonglong2 qa = __ldg(wpA + i);
            ulonglong2 qb = __ldg(wpB + i);
            wa[2 * i] = qa.x; wa[2 * i + 1] = qa.y;
            wb[2 * i] = qb.x; wb[2 * i + 1] = qb.y;
        }
    }
    stgt[tid] = targets[b * NP + tid];

    const float4* dbase4 = (const float4*)(data + (size_t)b * NP * ND);
    ((float4*)srow[0])[tid] = __ldg(dbase4 + tid);   // preload tile 0
    __syncthreads();

    float4* mypart = g_part + ((size_t)b * NP * NCHUNK + chunk) * NWARP + warp;
    float cA = 0.0f, cB = 0.0f;   // exclusive prefix cumsums (<= 0)

    #pragma unroll 1
    for (int tile = 0; tile < NP / PTILE; ++tile) {
        const int buf = tile & 1;

        if (tile + 1 < NP / PTILE)   // prefetch next tile (~16 p's ahead)
            ((float4*)srow[buf ^ 1])[tid] = __ldg(dbase4 + (tile + 1) * 256 + tid);

        #pragma unroll 1
        for (int pp = 0; pp < PTILE; pp += 4) {
            const int p0 = tile * PTILE + pp;

            // ---- 8 dots: rows {p0..p0+3} x tasks {A, B} ----
            float dA[4], dB[4];
            #pragma unroll
            for (int k = 0; k < 4; ++k) {
                const ulonglong2* row = (const ulonglong2*)srow[buf][pp + k];
                u64 a0 = 0ull, a1 = 0ull, b0 = 0ull, b1 = 0ull;
                #pragma unroll
                for (int i = 0; i < 16; i += 2) {
                    ulonglong2 x = row[i];
                    ulonglong2 y = row[i + 1];
                    a0 = fma2(x.x, wa[2 * i],     a0);
                    a1 = fma2(x.y, wa[2 * i + 1], a1);
                    b0 = fma2(x.x, wb[2 * i],     b0);
                    b1 = fma2(x.y, wb[2 * i + 1], b1);
                    a0 = fma2(y.x, wa[2 * i + 2], a0);
                    a1 = fma2(y.y, wa[2 * i + 3], a1);
                    b0 = fma2(y.x, wb[2 * i + 2], b0);
                    b1 = fma2(y.y, wb[2 * i + 3], b1);
                }
                a0 = add2(a0, a1);
                b0 = add2(b0, b1);
                const float2 va = u2f(a0);
                const float2 vb = u2f(b0);
                dA[k] = va.x + va.y;
                dB[k] = vb.x + vb.y;
            }

            // ---- sequential logit/score updates (short chain) ----
            float lA[4], lB[4];
            #pragma unroll
            for (int k = 0; k < 4; ++k) {
                lA[k] = cA; lB[k] = cB;
                const float tg = stgt[p0 + k];
                const float eA = tg - dA[k];
                const float eB = tg - dB[k];
                cA = fmaf(-0.5f * eA, eA, cA);
                cB = fmaf(-0.5f * eB, eB, cB);
            }

            // ---- four softmax partials, reduction chains interleaved ----
            float m[4], S[4], V[4];
            #pragma unroll
            for (int k = 0; k < 4; ++k) {
                m[k] = warp_max_nonpos(fmaxf(lA[k], lB[k]));
                const float eA = mufu_exp(lA[k] - m[k]);   // leader -> 1
                const float eB = mufu_exp(lB[k] - m[k]);
                S[k] = eA + eB;
                V[k] = fmaf(eA, dA[k], eB * dB[k]);
            }
            #pragma unroll
            for (int off = 16; off > 0; off >>= 1) {
                #pragma unroll
                for (int k = 0; k < 4; ++k) {
                    S[k] += __shfl_xor_sync(0xffffffffu, S[k], off);
                    V[k] += __shfl_xor_sync(0xffffffffu, V[k], off);
                }
            }

            if (lane == 0) {
                #pragma unroll
                for (int k = 0; k < 4; ++k)
                    mypart[(size_t)(p0 + k) * NPART] =
                        make_float4(m[k], S[k], V[k], 0.0f);
            }
        }
        __syncthreads();   // tile consumed; prefetch writes visible
    }

    // ---------------- fused combine: last chunk-CTA per b ----------------
    if (tid == 0) {
        __threadfence();                       // publish this CTA's partials
        int old = atomicAdd(&g_ready[b], 1);
        sIsLast = (old == NCHUNK - 1);
    }
    __syncthreads();
    if (!sIsLast) return;

    __threadfence();   // make siblings' partials visible

    // 8 warps x 32 p's each: LSE-merge 64 partials per (b,p)
    #pragma unroll 1
    for (int i = 0; i < NP / NWARP; ++i) {
        const int p = warp * (NP / NWARP) + i;
        const float4* pp_ = g_part + ((size_t)b * NP + p) * NPART + lane * 2;
        float4 l0 = pp_[0], l1 = pp_[1];

        float mm = warp_max_nonpos(fmaxf(l0.x, l1.x));   // all <= 0
        float e0 = mufu_exp(l0.x - mm);
        float e1 = mufu_exp(l1.x - mm);
        float S = fmaf(e0, l0.y, e1 * l1.y);
        float V = fmaf(e0, l0.z, e1 * l1.z);
        #pragma unroll
        for (int off = 16; off > 0; off >>= 1) {
            S += __shfl_xor_sync(0xffffffffu, S, off);
            V += __shfl_xor_sync(0xffffffffu, V, off);
        }
        if (lane == 0) out[b * NP + p] = V / S;
    }

    __syncthreads();
    if (tid == 0) g_ready[b] = 0;   // reset for next call / graph replay
}

// ------------------------------------------------------------------
extern "C" void kernel_launch(void* const* d_in, const int* in_sizes, int n_in,
                              void* d_out, int out_size)
{
    (void)out_size;
    const float* data      = (const float*)d_in[0];
    const float* targets   = (const float*)d_in[1];
    const float* task_pool = (const float*)d_in[2];
    for (int i = 0; i < n_in; ++i) {
        if (in_sizes[i] == NB * NP * ND)      data      = (const float*)d_in[i];
        else if (in_sizes[i] == NB * NP)      targets   = (const float*)d_in[i];
        else if (in_sizes[i] == NT * ND)      task_pool = (const float*)d_in[i];
    }
    float* out = (float*)d_out;   // (B, P)

    dim3 grid(NCHUNK, NB);
    mmse_main<<<grid, 256>>>(data, targets, task_pool, out);
}

// round 12
// speedup vs baseline: 1.1248x; 1.1248x over previous
#include <cuda_runtime.h>

#define NB 32
#define NP 256
#define ND 64
#define NT 4096
#define TCHUNK 512   // tasks per CTA (2 per thread)
#define NCHUNK 8     // NT / TCHUNK
#define NWARP 8      // warps per CTA
#define NGROUP 4     // 8-lane groups per warp
#define NPART (NCHUNK * NWARP * NGROUP)   // 256 partials per (b,p)
#define PTILE 16     // p rows staged per smem tile

#define NEG_HALF_LOG2E (-0.72134752044448170f)   // -0.5 * log2(e)

typedef unsigned long long u64;

// Per-8-lane-group partials: (warp max m [log2 units], S, V, pad)
__device__ float4 g_part[NB * NP * NPART];

// ---------- packed f32x2 helpers ----------
__device__ __forceinline__ u64 fma2(u64 a, u64 b, u64 acc) {
    u64 r;
    asm("fma.rn.f32x2 %0, %1, %2, %3;" : "=l"(r) : "l"(a), "l"(b), "l"(acc));
    return r;
}
__device__ __forceinline__ u64 add2(u64 a, u64 b) {
    u64 r;
    asm("add.rn.f32x2 %0, %1, %2;" : "=l"(r) : "l"(a), "l"(b));
    return r;
}
__device__ __forceinline__ float2 u2f(u64 a) {
    float2 r;
    asm("mov.b64 {%0, %1}, %2;" : "=f"(r.x), "=f"(r.y) : "l"(a));
    return r;
}

// Warp float-max for values <= 0 in ONE instruction (u32-min over raw bits;
// +0.0 -> 0x00000000, negatives order inversely as u32).
__device__ __forceinline__ float warp_max_nonpos(float x) {
    return __uint_as_float(__reduce_min_sync(0xffffffffu, __float_as_uint(x)));
}

// 2^x via MUFU (logits kept in log2 domain -> no pre-multiply).
__device__ __forceinline__ float ex2f(float x) {
    float r;
    asm("ex2.approx.f32 %0, %1;" : "=f"(r) : "f"(x));
    return r;
}

// ------------------------------------------------------------------
// CTA = (t-chunk, b). TWO tasks per thread; 2 p's per inner step.
// Per p: one warp redux for the max, then 8-lane-group (S,V) partials
// (3 SHFL levels). Logits in log2 units. No block barriers in scan.
// ------------------------------------------------------------------
__global__ void __launch_bounds__(256, 1)
mmse_main(const float* __restrict__ data,
          const float* __restrict__ targets,
          const float* __restrict__ task_pool)
{
    const int chunk = blockIdx.x;
    const int b     = blockIdx.y;
    const int tid   = threadIdx.x;
    const int lane  = tid & 31;
    const int warp  = tid >> 5;
    const int tA    = chunk * TCHUNK + tid;
    const int tB    = tA + 256;

    __shared__ float stgt[NP];
    __shared__ float srow[2][PTILE][ND];   // 2 x 4KB row tiles

    // Two W columns as packed f32x2 (128 registers)
    u64 wa[32], wb[32];
    {
        const ulonglong2* wpA = (const ulonglong2*)(task_pool + (size_t)tA * ND);
        const ulonglong2* wpB = (const ulonglong2*)(task_pool + (size_t)tB * ND);
        #pragma unroll
        for (int i = 0; i < 16; ++i) {
            ulonglong2 qa = __ldg(wpA + i);
            ulonglong2 qb = __ldg(wpB + i);
            wa[2 * i] = qa.x; wa[2 * i + 1] = qa.y;
            wb[2 * i] = qb.x; wb[2 * i + 1] = qb.y;
        }
    }
    stgt[tid] = targets[b * NP + tid];

    const float4* dbase4 = (const float4*)(data + (size_t)b * NP * ND);
    ((float4*)srow[0])[tid] = __ldg(dbase4 + tid);   // preload tile 0
    __syncthreads();

    // group leader lanes (0,8,16,24) write their group's partial
    float4* mypart = g_part
        + ((size_t)b * NP * NCHUNK + chunk) * (NWARP * NGROUP)
        + warp * NGROUP + (lane >> 3);

    float cA = 0.0f, cB = 0.0f;   // prefix cumsums, log2 units (<= 0)

    #pragma unroll 1
    for (int tile = 0; tile < NP / PTILE; ++tile) {
        const int buf = tile & 1;

        if (tile + 1 < NP / PTILE)   // prefetch next tile (~16 p's ahead)
            ((float4*)srow[buf ^ 1])[tid] = __ldg(dbase4 + (tile + 1) * 256 + tid);

        #pragma unroll 1
        for (int pp = 0; pp < PTILE; pp += 2) {
            const int p0 = tile * PTILE + pp;

            // ---- 4 dots: rows {p0, p0+1} x tasks {A, B} ----
            float dA[2], dB[2];
            #pragma unroll
            for (int k = 0; k < 2; ++k) {
                const ulonglong2* row = (const ulonglong2*)srow[buf][pp + k];
                u64 a0 = 0ull, a1 = 0ull, b0 = 0ull, b1 = 0ull;
                #pragma unroll
                for (int i = 0; i < 16; i += 2) {
                    ulonglong2 x = row[i];
                    ulonglong2 y = row[i + 1];
                    a0 = fma2(x.x, wa[2 * i],     a0);
                    a1 = fma2(x.y, wa[2 * i + 1], a1);
                    b0 = fma2(x.x, wb[2 * i],     b0);
                    b1 = fma2(x.y, wb[2 * i + 1], b1);
                    a0 = fma2(y.x, wa[2 * i + 2], a0);
                    a1 = fma2(y.y, wa[2 * i + 3], a1);
                    b0 = fma2(y.x, wb[2 * i + 2], b0);
                    b1 = fma2(y.y, wb[2 * i + 3], b1);
                }
                a0 = add2(a0, a1);
                b0 = add2(b0, b1);
                const float2 va = u2f(a0);
                const float2 vb = u2f(b0);
                dA[k] = va.x + va.y;
                dB[k] = vb.x + vb.y;
            }

            // ---- logits + score updates (log2 domain) ----
            float lA[2], lB[2];
            #pragma unroll
            for (int k = 0; k < 2; ++k) {
                lA[k] = cA; lB[k] = cB;
                const float tg = stgt[p0 + k];
                const float eA = tg - dA[k];
                const float eB = tg - dB[k];
                cA = fmaf(NEG_HALF_LOG2E * eA, eA, cA);
                cB = fmaf(NEG_HALF_LOG2E * eB, eB, cB);
            }

            // ---- two partial sets: warp max + 8-lane-group (S,V) ----
            float m[2], S[2], V[2];
            #pragma unroll
            for (int k = 0; k < 2; ++k) {
                m[k] = warp_max_nonpos(fmaxf(lA[k], lB[k]));
                const float eA = ex2f(lA[k] - m[k]);   // warp leader -> 1
                const float eB = ex2f(lB[k] - m[k]);
                S[k] = eA + eB;
                V[k] = fmaf(eA, dA[k], eB * dB[k]);
            }
            #pragma unroll
            for (int off = 1; off <= 4; off <<= 1) {   // 3 levels: 8-lane groups
                #pragma unroll
                for (int k = 0; k < 2; ++k) {
                    S[k] += __shfl_xor_sync(0xffffffffu, S[k], off);
                    V[k] += __shfl_xor_sync(0xffffffffu, V[k], off);
                }
            }

            if ((lane & 7) == 0) {   // lanes 0,8,16,24: coalesced 64B per warp
                mypart[(size_t)p0 * NPART]       = make_float4(m[0], S[0], V[0], 0.0f);
                mypart[(size_t)(p0 + 1) * NPART] = make_float4(m[1], S[1], V[1], 0.0f);
            }
        }
        __syncthreads();   // tile consumed; prefetch writes visible
    }
}

// ------------------------------------------------------------------
// Combine: one warp per (b,p); LSE-merge its 256 group partials.
// ------------------------------------------------------------------
__global__ void __launch_bounds__(256)
mmse_combine(float* __restrict__ out)
{
    const int warp = threadIdx.x >> 5;
    const int lane = threadIdx.x & 31;
    const int idx  = blockIdx.x * 8 + warp;    // b*NP + p
    const float4* pp = g_part + (size_t)idx * NPART;

    float4 l[8];
    #pragma unroll
    for (int j = 0; j < 8; ++j)
        l[j] = pp[lane + 32 * j];   // coalesced 512B per j

    float mx = l[0].x;
    #pragma unroll
    for (int j = 1; j < 8; ++j) mx = fmaxf(mx, l[j].x);
    mx = warp_max_nonpos(mx);       // all m's <= 0

    float S = 0.0f, V = 0.0f;
    #pragma unroll
    for (int j = 0; j < 8; ++j) {
        const float e = ex2f(l[j].x - mx);
        S = fmaf(e, l[j].y, S);
        V = fmaf(e, l[j].z, V);
    }
    #pragma unroll
    for (int off = 16; off > 0; off >>= 1) {
        S += __shfl_xor_sync(0xffffffffu, S, off);
        V += __shfl_xor_sync(0xffffffffu, V, off);
    }

    if (lane == 0) out[idx] = V / S;
}

// ------------------------------------------------------------------
extern "C" void kernel_launch(void* const* d_in, const int* in_sizes, int n_in,
                              void* d_out, int out_size)
{
    (void)out_size;
    const float* data      = (const float*)d_in[0];
    const float* targets   = (const float*)d_in[1];
    const float* task_pool = (const float*)d_in[2];
    for (int i = 0; i < n_in; ++i) {
        if (in_sizes[i] == NB * NP * ND)      data      = (const float*)d_in[i];
        else if (in_sizes[i] == NB * NP)      targets   = (const float*)d_in[i];
        else if (in_sizes[i] == NT * ND)      task_pool = (const float*)d_in[i];
    }
    float* out = (float*)d_out;   // (B, P)

    dim3 grid(NCHUNK, NB);
    mmse_main<<<grid, 256>>>(data, targets, task_pool);
    mmse_combine<<<(NB * NP) / 8, 256>>>(out);
}